// round 1
// baseline (speedup 1.0000x reference)
#include <cuda_runtime.h>

// Q = L @ L^T where L is lower-triangular 3x3 scattered from packed [a,b,c,d,e,f]:
//   L = [[a,0,0],[b,c,0],[d,e,f]]
//   Q00=a*a  Q01=a*b      Q02=a*d
//   Q10=a*b  Q11=b*b+c*c  Q12=b*d+c*e
//   Q20=a*d  Q21=b*d+c*e  Q22=d*d+e*e+f*f
//
// Memory-bound: 24B in, 36B out per row. Each thread handles 4 rows so that
// both input (24 floats) and output (36 floats) are whole float4 multiples,
// giving fully-aligned vectorized LDG.128 / STG.128 with 100% sector use.

__device__ __forceinline__ void row_to_q(const float* __restrict__ v, float* __restrict__ o) {
    const float a = v[0], b = v[1], c = v[2], d = v[3], e = v[4], f = v[5];
    const float ab = a * b;
    const float ad = a * d;
    const float bdce = b * d + c * e;
    o[0] = a * a;
    o[1] = ab;
    o[2] = ad;
    o[3] = ab;
    o[4] = b * b + c * c;
    o[5] = bdce;
    o[6] = ad;
    o[7] = bdce;
    o[8] = d * d + e * e + f * f;
}

__global__ void chol_to_cov_vec4(const float4* __restrict__ in4,
                                 float4* __restrict__ out4,
                                 int nquads)  // nquads = n_rows / 4
{
    const int i = blockIdx.x * blockDim.x + threadIdx.x;
    if (i >= nquads) return;

    // 4 rows = 24 input floats = 6 float4 (contiguous, aligned)
    float v[24];
    const float4* ip = in4 + (size_t)i * 6;
#pragma unroll
    for (int k = 0; k < 6; k++) {
        const float4 t = ip[k];
        v[4 * k + 0] = t.x;
        v[4 * k + 1] = t.y;
        v[4 * k + 2] = t.z;
        v[4 * k + 3] = t.w;
    }

    // 4 rows = 36 output floats = 9 float4 (contiguous, aligned)
    float o[36];
#pragma unroll
    for (int r = 0; r < 4; r++) {
        row_to_q(v + 6 * r, o + 9 * r);
    }

    float4* op = out4 + (size_t)i * 9;
#pragma unroll
    for (int k = 0; k < 9; k++) {
        float4 t;
        t.x = o[4 * k + 0];
        t.y = o[4 * k + 1];
        t.z = o[4 * k + 2];
        t.w = o[4 * k + 3];
        op[k] = t;
    }
}

// Scalar tail for rows not covered by the vectorized kernel (n % 4 != 0).
__global__ void chol_to_cov_tail(const float* __restrict__ in,
                                 float* __restrict__ out,
                                 int start_row, int n_rows)
{
    const int r = start_row + blockIdx.x * blockDim.x + threadIdx.x;
    if (r >= n_rows) return;
    float v[6], o[9];
#pragma unroll
    for (int k = 0; k < 6; k++) v[k] = in[(size_t)r * 6 + k];
    row_to_q(v, o);
#pragma unroll
    for (int k = 0; k < 9; k++) out[(size_t)r * 9 + k] = o[k];
}

extern "C" void kernel_launch(void* const* d_in, const int* in_sizes, int n_in,
                              void* d_out, int out_size)
{
    const float* in = (const float*)d_in[0];
    float* out = (float*)d_out;
    const int n_rows = in_sizes[0] / 6;

    const int nquads = n_rows / 4;
    if (nquads > 0) {
        const int threads = 256;
        const int blocks = (nquads + threads - 1) / threads;
        chol_to_cov_vec4<<<blocks, threads>>>((const float4*)in, (float4*)out, nquads);
    }
    const int done = nquads * 4;
    if (done < n_rows) {
        const int rem = n_rows - done;
        chol_to_cov_tail<<<(rem + 127) / 128, 128>>>(in, out, done, n_rows);
    }
}

// round 2
// speedup vs baseline: 1.6827x; 1.6827x over previous
#include <cuda_runtime.h>

// Q = L @ L^T, L lower-triangular 3x3 from packed [a,b,c,d,e,f]:
//   Q00=a*a  Q01=a*b      Q02=a*d
//   Q10=a*b  Q11=b*b+c*c  Q12=b*d+c*e
//   Q20=a*d  Q21=b*d+c*e  Q22=d*d+e*e+f*f
//
// Pure streaming op (24B in / 36B out per row). The R1 kernel's per-thread
// contiguous float4 access made each LDG/STG touch ~32 distinct 128B lines
// per warp instruction (L1 wavefront bound, DRAM only 43%). This version
// stages through shared memory so that every global LDG.128/STG.128 is
// warp-dense (4 lines/instruction):
//   gmem --(dense f4)--> smem_in --(compute)--> smem_out --(dense f4)--> gmem

#define TPB 128              // threads per block
#define ROWS_PB 512          // rows per block (512*6/4=768 f4 in, 512*9/4=1152 f4 out)
#define IN_F4_PT 6           // 768 / 128
#define OUT_F4_PT 9          // 1152 / 128
#define ROWS_PT 4            // 512 / 128

__device__ __forceinline__ void row_to_q(const float* __restrict__ v, float* __restrict__ o) {
    const float a = v[0], b = v[1], c = v[2], d = v[3], e = v[4], f = v[5];
    const float ab = a * b;
    const float ad = a * d;
    const float bdce = fmaf(b, d, c * e);
    o[0] = a * a;
    o[1] = ab;
    o[2] = ad;
    o[3] = ab;
    o[4] = fmaf(b, b, c * c);
    o[5] = bdce;
    o[6] = ad;
    o[7] = bdce;
    o[8] = fmaf(d, d, fmaf(e, e, f * f));
}

__global__ __launch_bounds__(TPB) void chol_to_cov_staged(const float4* __restrict__ in4,
                                                          float4* __restrict__ out4)
{
    __shared__ float s_in[ROWS_PB * 6];   // 12 KB
    __shared__ float s_out[ROWS_PB * 9];  // 18 KB

    const int t = threadIdx.x;
    const size_t b = blockIdx.x;

    // Phase 1: dense coalesced load gmem -> smem (each warp LDG.128 = 4 lines)
    const float4* ip = in4 + b * (ROWS_PB * 6 / 4);
    float4* si4 = reinterpret_cast<float4*>(s_in);
#pragma unroll
    for (int k = 0; k < IN_F4_PT; k++)
        si4[t + TPB * k] = ip[t + TPB * k];
    __syncthreads();

    // Phase 2: compute. Thread t handles rows t, t+128, t+256, t+384.
    // smem reads: lane stride 6 floats -> 2-way bank conflict (cheap).
    // smem writes: lane stride 9 floats -> conflict-free.
#pragma unroll
    for (int j = 0; j < ROWS_PT; j++) {
        const int r = t + TPB * j;
        float v[6], o[9];
#pragma unroll
        for (int k = 0; k < 6; k++) v[k] = s_in[r * 6 + k];
        row_to_q(v, o);
#pragma unroll
        for (int k = 0; k < 9; k++) s_out[r * 9 + k] = o[k];
    }
    __syncthreads();

    // Phase 3: dense coalesced store smem -> gmem
    float4* op = out4 + b * (ROWS_PB * 9 / 4);
    const float4* so4 = reinterpret_cast<const float4*>(s_out);
#pragma unroll
    for (int k = 0; k < OUT_F4_PT; k++)
        op[t + TPB * k] = so4[t + TPB * k];
}

// Scalar tail for the (< ROWS_PB) remainder rows.
__global__ void chol_to_cov_tail(const float* __restrict__ in,
                                 float* __restrict__ out,
                                 int start_row, int n_rows)
{
    const int r = start_row + blockIdx.x * blockDim.x + threadIdx.x;
    if (r >= n_rows) return;
    float v[6], o[9];
#pragma unroll
    for (int k = 0; k < 6; k++) v[k] = in[(size_t)r * 6 + k];
    row_to_q(v, o);
#pragma unroll
    for (int k = 0; k < 9; k++) out[(size_t)r * 9 + k] = o[k];
}

extern "C" void kernel_launch(void* const* d_in, const int* in_sizes, int n_in,
                              void* d_out, int out_size)
{
    const float* in = (const float*)d_in[0];
    float* out = (float*)d_out;
    const int n_rows = in_sizes[0] / 6;

    const int full_blocks = n_rows / ROWS_PB;
    if (full_blocks > 0) {
        chol_to_cov_staged<<<full_blocks, TPB>>>((const float4*)in, (float4*)out);
    }
    const int done = full_blocks * ROWS_PB;
    if (done < n_rows) {
        const int rem = n_rows - done;
        chol_to_cov_tail<<<(rem + 127) / 128, 128>>>(in, out, done, n_rows);
    }
}

// round 3
// speedup vs baseline: 1.7077x; 1.0148x over previous
#include <cuda_runtime.h>

// Q = L @ L^T, L lower-triangular 3x3 from packed [a,b,c,d,e,f]:
//   Q00=a*a  Q01=a*b      Q02=a*d
//   Q10=a*b  Q11=b*b+c*c  Q12=b*d+c*e
//   Q20=a*d  Q21=b*d+c*e  Q22=d*d+e*e+f*f
//
// Three-phase smem-staged streaming kernel. R2 showed DRAM=68.5% with only
// 28 warps/SM (31KB smem). This version shrinks the tile to 256 rows
// (15KB smem, 2 rows/thread) to roughly double resident warps and total
// in-flight global loads per SM. Streaming cache hints (ldcs/stcs) since
// there is zero data reuse.

#define TPB 128
#define ROWS_PB 256
#define IN_F4 (ROWS_PB * 6 / 4)    // 384 -> 3 per thread
#define OUT_F4 (ROWS_PB * 9 / 4)   // 576 -> 4.5 per thread

__device__ __forceinline__ void row_to_q(const float* __restrict__ v, float* __restrict__ o) {
    const float a = v[0], b = v[1], c = v[2], d = v[3], e = v[4], f = v[5];
    const float ab = a * b;
    const float ad = a * d;
    const float bdce = fmaf(b, d, c * e);
    o[0] = a * a;
    o[1] = ab;
    o[2] = ad;
    o[3] = ab;
    o[4] = fmaf(b, b, c * c);
    o[5] = bdce;
    o[6] = ad;
    o[7] = bdce;
    o[8] = fmaf(d, d, fmaf(e, e, f * f));
}

__global__ __launch_bounds__(TPB) void chol_to_cov_staged(const float4* __restrict__ in4,
                                                          float4* __restrict__ out4)
{
    __shared__ float s_in[ROWS_PB * 6];   // 6 KB
    __shared__ float s_out[ROWS_PB * 9];  // 9 KB

    const int t = threadIdx.x;
    const size_t b = blockIdx.x;

    // Phase 1: dense coalesced gmem -> smem (3 LDG.128 per thread, front-batched)
    const float4* ip = in4 + b * IN_F4;
    float4* si4 = reinterpret_cast<float4*>(s_in);
#pragma unroll
    for (int k = 0; k < 3; k++)
        si4[t + TPB * k] = __ldcs(ip + t + TPB * k);
    __syncthreads();

    // Phase 2: compute 2 rows per thread.
    // reads stride 6 (2-way conflict), writes stride 9 (conflict-free).
#pragma unroll
    for (int j = 0; j < 2; j++) {
        const int r = t + TPB * j;
        float v[6], o[9];
#pragma unroll
        for (int k = 0; k < 6; k++) v[k] = s_in[r * 6 + k];
        row_to_q(v, o);
#pragma unroll
        for (int k = 0; k < 9; k++) s_out[r * 9 + k] = o[k];
    }
    __syncthreads();

    // Phase 3: dense coalesced smem -> gmem (4 full STG.128 + half iteration)
    float4* op = out4 + b * OUT_F4;
    const float4* so4 = reinterpret_cast<const float4*>(s_out);
#pragma unroll
    for (int k = 0; k < 4; k++)
        __stcs(op + t + TPB * k, so4[t + TPB * k]);
    if (t < OUT_F4 - 4 * TPB)  // remaining 64 float4
        __stcs(op + t + 4 * TPB, so4[t + 4 * TPB]);
}

// Scalar tail for the (< ROWS_PB) remainder rows.
__global__ void chol_to_cov_tail(const float* __restrict__ in,
                                 float* __restrict__ out,
                                 int start_row, int n_rows)
{
    const int r = start_row + blockIdx.x * blockDim.x + threadIdx.x;
    if (r >= n_rows) return;
    float v[6], o[9];
#pragma unroll
    for (int k = 0; k < 6; k++) v[k] = in[(size_t)r * 6 + k];
    row_to_q(v, o);
#pragma unroll
    for (int k = 0; k < 9; k++) out[(size_t)r * 9 + k] = o[k];
}

extern "C" void kernel_launch(void* const* d_in, const int* in_sizes, int n_in,
                              void* d_out, int out_size)
{
    const float* in = (const float*)d_in[0];
    float* out = (float*)d_out;
    const int n_rows = in_sizes[0] / 6;

    const int full_blocks = n_rows / ROWS_PB;
    if (full_blocks > 0) {
        chol_to_cov_staged<<<full_blocks, TPB>>>((const float4*)in, (float4*)out);
    }
    const int done = full_blocks * ROWS_PB;
    if (done < n_rows) {
        const int rem = n_rows - done;
        chol_to_cov_tail<<<(rem + 127) / 128, 128>>>(in, out, done, n_rows);
    }
}